// round 4
// baseline (speedup 1.0000x reference)
#include <cuda_runtime.h>
#include <cstdint>

// Problem constants (from reference: x[32,64,4096], w[128,64,64], b[128])
#define N_BATCH 32
#define C_IN    64
#define W_IN    4096
#define F_OUT   128
#define K_W     64
#define OUT_W   (W_IN - K_W + 1)     // 4033
#define K_RED   (C_IN * K_W)         // 4096

// Tiling
#define BM      128                  // output t positions per block
#define TW      192                  // x window stride (BM + 64), padded
#define WS      36                   // w_s row stride (32 + 4) -> conflict-free
#define BK      32                   // reduction chunk (half of one channel's taps)
#define NCHUNK  (K_RED / BK)         // 128

#define XS_WORDS (C_IN * TW)                      // 12288 words = 48 KB
#define WSM_WORDS (F_OUT * WS)                    // 4608 words  = 18 KB
#define SMEM_BYTES ((XS_WORDS + 2 * WSM_WORDS) * 4)   // 86016 B

// Round-to-nearest fp32 -> tf32 (unbiased; raw truncation would bias the
// K=4096 reduction by ~1e-3 and fail the tolerance).
__device__ __forceinline__ unsigned f2tf(float f) {
    unsigned u;
    asm("cvt.rna.tf32.f32 %0, %1;" : "=r"(u) : "f"(f));
    return u;
}

__device__ __forceinline__ void mma_tf32(float c[4],
                                         unsigned a0, unsigned a1, unsigned a2, unsigned a3,
                                         unsigned b0, unsigned b1) {
    asm volatile(
        "mma.sync.aligned.m16n8k8.row.col.f32.tf32.tf32.f32 "
        "{%0,%1,%2,%3}, {%4,%5,%6,%7}, {%8,%9}, {%0,%1,%2,%3};"
        : "+f"(c[0]), "+f"(c[1]), "+f"(c[2]), "+f"(c[3])
        : "r"(a0), "r"(a1), "r"(a2), "r"(a3), "r"(b0), "r"(b1));
}

extern "C" __global__ void __launch_bounds__(256)
conv1d_tf32_kernel(const float* __restrict__ x,
                   const float* __restrict__ w,
                   const float* __restrict__ bias,
                   float* __restrict__ out)
{
    extern __shared__ unsigned smem[];
    unsigned* xs  = smem;                 // [C_IN][TW]  tf32 bits
    unsigned* wsm = smem + XS_WORDS;      // [2][F_OUT][WS] tf32 bits

    const int tid  = threadIdx.x;
    const int lane = tid & 31;
    const int wid  = tid >> 5;
    const int gid  = lane >> 2;           // "groupID" in mma fragment terms
    const int tig  = lane & 3;            // "threadID in group"
    const int warp_m = wid & 1;           // 2 m-tiles of 64
    const int warp_n = wid >> 1;          // 4 n-tiles of 32

    const int t0 = blockIdx.x * BM;       // output t base
    const int n  = blockIdx.y;            // batch index

    const float* xg = x + (size_t)n * C_IN * W_IN;

    // ---- Load x window [64 x 192] (t0 .. t0+191), zero-pad past W, cvt to tf32 ----
    for (int i = tid; i < XS_WORDS; i += 256) {
        int c  = i / TW;
        int tw = i - c * TW;
        int t  = t0 + tw;
        float v = (t < W_IN) ? xg[c * W_IN + t] : 0.0f;
        xs[i] = f2tf(v);
    }

    // ---- Preload w chunk 0 into registers, store to buffer 0 ----
    // chunk kk0 = chunk*32 covers reduction indices kk = c*64 + k,
    // w[f][c][k] lives at w[f*4096 + kk]  (contiguous in kk).
    float4 pf[4];
#pragma unroll
    for (int j = 0; j < 4; ++j) {
        int g = j * 256 + tid;            // float4 index within chunk
        int f = g >> 3;                   // 8 float4 per filter row
        int q = g & 7;
        pf[j] = *reinterpret_cast<const float4*>(w + (size_t)f * K_RED + q * 4);
    }
#pragma unroll
    for (int j = 0; j < 4; ++j) {
        int g = j * 256 + tid;
        int f = g >> 3;
        int q = g & 7;
        uint4 v = make_uint4(f2tf(pf[j].x), f2tf(pf[j].y), f2tf(pf[j].z), f2tf(pf[j].w));
        *reinterpret_cast<uint4*>(wsm + f * WS + q * 4) = v;
    }
    __syncthreads();

    float acc[4][4][4];
#pragma unroll
    for (int mf = 0; mf < 4; ++mf)
#pragma unroll
        for (int nf = 0; nf < 4; ++nf)
#pragma unroll
            for (int r = 0; r < 4; ++r)
                acc[mf][nf][r] = 0.0f;

    // ---- Main loop over 128 reduction chunks (c = chunk>>1, k base = (chunk&1)*32) ----
    for (int chunk = 0; chunk < NCHUNK; ++chunk) {
        // prefetch next w chunk from gmem while computing
        if (chunk + 1 < NCHUNK) {
            const int kk0 = (chunk + 1) * BK;
#pragma unroll
            for (int j = 0; j < 4; ++j) {
                int g = j * 256 + tid;
                int f = g >> 3;
                int q = g & 7;
                pf[j] = *reinterpret_cast<const float4*>(w + (size_t)f * K_RED + kk0 + q * 4);
            }
        }

        const unsigned* wb = wsm + (chunk & 1) * WSM_WORDS;
        const int c  = chunk >> 1;
        const int kb = (chunk & 1) << 5;           // 0 or 32
        const unsigned* xc = xs + c * TW;

#pragma unroll
        for (int s = 0; s < 4; ++s) {              // 4 k-steps of 8
            const int kcol = kb + s * 8 + tig;     // k for A fragment cols
            unsigned a[4][4];
#pragma unroll
            for (int mf = 0; mf < 4; ++mf) {
                const int r = warp_m * 64 + mf * 16 + gid;   // t row
                const unsigned* p = xc + r + kcol;           // x[c][t0 + r + k]
                a[mf][0] = p[0];      // (row,   col)
                a[mf][1] = p[8];      // (row+8, col)
                a[mf][2] = p[4];      // (row,   col+4)
                a[mf][3] = p[12];     // (row+8, col+4)
            }
            const int kkl = s * 8 + tig;           // local kk within chunk
            unsigned bfr[4][2];
#pragma unroll
            for (int nf = 0; nf < 4; ++nf) {
                const int f = warp_n * 32 + nf * 8 + gid;
                bfr[nf][0] = wb[f * WS + kkl];
                bfr[nf][1] = wb[f * WS + kkl + 4];
            }
#pragma unroll
            for (int mf = 0; mf < 4; ++mf)
#pragma unroll
                for (int nf = 0; nf < 4; ++nf)
                    mma_tf32(acc[mf][nf], a[mf][0], a[mf][1], a[mf][2], a[mf][3],
                             bfr[nf][0], bfr[nf][1]);
        }

        // store prefetched chunk into the other buffer (safe: everyone finished
        // reading it at the sync that ended the previous iteration)
        if (chunk + 1 < NCHUNK) {
            unsigned* wn = wsm + ((chunk + 1) & 1) * WSM_WORDS;
#pragma unroll
            for (int j = 0; j < 4; ++j) {
                int g = j * 256 + tid;
                int f = g >> 3;
                int q = g & 7;
                uint4 v = make_uint4(f2tf(pf[j].x), f2tf(pf[j].y), f2tf(pf[j].z), f2tf(pf[j].w));
                *reinterpret_cast<uint4*>(wn + f * WS + q * 4) = v;
            }
        }
        __syncthreads();
    }

    // ---- Epilogue: add bias, store out[n][f][t] ----
    float* outg = out + (size_t)n * F_OUT * OUT_W;
#pragma unroll
    for (int nf = 0; nf < 4; ++nf) {
        const int f0 = warp_n * 32 + nf * 8 + 2 * tig;
        const float b0v = bias[f0];
        const float b1v = bias[f0 + 1];
#pragma unroll
        for (int mf = 0; mf < 4; ++mf) {
            const int t_lo = t0 + warp_m * 64 + mf * 16 + gid;
            const int t_hi = t_lo + 8;
            if (t_lo < OUT_W) {
                outg[(size_t)f0 * OUT_W + t_lo]       = acc[mf][nf][0] + b0v;
                outg[(size_t)(f0 + 1) * OUT_W + t_lo] = acc[mf][nf][1] + b1v;
            }
            if (t_hi < OUT_W) {
                outg[(size_t)f0 * OUT_W + t_hi]       = acc[mf][nf][2] + b0v;
                outg[(size_t)(f0 + 1) * OUT_W + t_hi] = acc[mf][nf][3] + b1v;
            }
        }
    }
}

extern "C" void kernel_launch(void* const* d_in, const int* in_sizes, int n_in,
                              void* d_out, int out_size) {
    // Identify inputs by element count (robust to metadata ordering):
    // x: 32*64*4096 = 8388608, w: 128*64*64 = 524288, b: 128
    const float* x = nullptr;
    const float* w = nullptr;
    const float* b = nullptr;
    for (int i = 0; i < n_in; ++i) {
        const int s = in_sizes[i];
        if (s == N_BATCH * C_IN * W_IN)      x = (const float*)d_in[i];
        else if (s == F_OUT * C_IN * K_W)    w = (const float*)d_in[i];
        else if (s == F_OUT)                 b = (const float*)d_in[i];
    }

    cudaFuncSetAttribute(conv1d_tf32_kernel,
                         cudaFuncAttributeMaxDynamicSharedMemorySize, SMEM_BYTES);

    dim3 grid((OUT_W + BM - 1) / BM, N_BATCH);   // (32, 32)
    conv1d_tf32_kernel<<<grid, 256, SMEM_BYTES>>>(x, w, b, (float*)d_out);
}

// round 7
// speedup vs baseline: 1.1433x; 1.1433x over previous
#include <cuda_runtime.h>
#include <cstdint>

// Problem constants (from reference: x[32,64,4096], w[128,64,64], b[128])
#define N_BATCH 32
#define C_IN    64
#define W_IN    4096
#define F_OUT   128
#define K_W     64
#define OUT_W   (W_IN - K_W + 1)     // 4033
#define K_RED   (C_IN * K_W)         // 4096

// Tiling
#define BM      128                  // output t positions per block
#define TW      192                  // x window stride (BM + 64), padded
#define WS      36                   // w_s row stride (32 + 4) -> conflict-free
#define BK      32                   // reduction chunk (half of one channel's taps)
#define NCHUNK  (K_RED / BK)         // 128

#define XS_WORDS  (C_IN * TW)                     // 12288 words = 48 KB
#define WSM_WORDS (F_OUT * WS)                    // 4608 words  = 18 KB
#define SMEM_BYTES ((XS_WORDS + 2 * WSM_WORDS) * 4)   // 86016 B

// Round-to-nearest fp32 -> tf32 (unbiased; raw truncation would bias the
// K=4096 reduction and blow the 1e-3 tolerance).
__device__ __forceinline__ unsigned f2tf(float f) {
    unsigned u;
    asm("cvt.rna.tf32.f32 %0, %1;" : "=r"(u) : "f"(f));
    return u;
}

__device__ __forceinline__ void mma_tf32(float c[4],
                                         unsigned a0, unsigned a1, unsigned a2, unsigned a3,
                                         unsigned b0, unsigned b1) {
    asm volatile(
        "mma.sync.aligned.m16n8k8.row.col.f32.tf32.tf32.f32 "
        "{%0,%1,%2,%3}, {%4,%5,%6,%7}, {%8,%9}, {%0,%1,%2,%3};"
        : "+f"(c[0]), "+f"(c[1]), "+f"(c[2]), "+f"(c[3])
        : "r"(a0), "r"(a1), "r"(a2), "r"(a3), "r"(b0), "r"(b1));
}

__device__ __forceinline__ void cp_async16(uint32_t smem_addr, const void* gptr) {
    asm volatile("cp.async.cg.shared.global [%0], [%1], 16;"
                 :: "r"(smem_addr), "l"(gptr));
}
__device__ __forceinline__ void cp_commit() {
    asm volatile("cp.async.commit_group;");
}
template <int N>
__device__ __forceinline__ void cp_wait() {
    asm volatile("cp.async.wait_group %0;" :: "n"(N));
}

extern "C" __global__ void __launch_bounds__(256, 2)
conv1d_tf32_kernel(const float* __restrict__ x,
                   const float* __restrict__ w,
                   const float* __restrict__ bias,
                   float* __restrict__ out)
{
    extern __shared__ unsigned smem[];
    unsigned* xs  = smem;                               // [C_IN][TW]  tf32 bits
    float*    wsm = reinterpret_cast<float*>(smem + XS_WORDS);  // [2][F_OUT][WS] raw fp32

    const int tid  = threadIdx.x;
    const int lane = tid & 31;
    const int wid  = tid >> 5;
    const int gid  = lane >> 2;           // mma fragment groupID
    const int tig  = lane & 3;            // mma fragment threadID-in-group
    const int warp_m = wid & 1;           // 2 m-tiles of 64
    const int warp_n = wid >> 1;          // 4 n-tiles of 32

    const int t0 = blockIdx.x * BM;       // output t base
    const int n  = blockIdx.y;            // batch index

    const float* xg = x + (size_t)n * C_IN * W_IN;

    // Per-thread cp.async slice: 4 x 16B per chunk. Thread handles
    // (f, q) pairs: g = j*256 + tid, f = g>>3, q = g&7.
    // Precompute smem byte addresses and gmem row pointers.
    uint32_t wsm_base = (uint32_t)__cvta_generic_to_shared(wsm);

    // ---- Kick off w chunk 0 copy ----
#pragma unroll
    for (int j = 0; j < 4; ++j) {
        int g = j * 256 + tid;
        int f = g >> 3;
        int q = g & 7;
        cp_async16(wsm_base + (uint32_t)(f * WS + q * 4) * 4,
                   w + (size_t)f * K_RED + q * 4);
    }
    cp_commit();

    // ---- Load x window [64 x 192] (t0 .. t0+191), zero-pad past W, cvt to tf32 ----
    for (int i = tid; i < XS_WORDS; i += 256) {
        int c  = i / TW;
        int tw = i - c * TW;
        int t  = t0 + tw;
        float v = (t < W_IN) ? xg[c * W_IN + t] : 0.0f;
        xs[i] = f2tf(v);
    }

    float acc[4][4][4];
#pragma unroll
    for (int mf = 0; mf < 4; ++mf)
#pragma unroll
        for (int nf = 0; nf < 4; ++nf)
#pragma unroll
            for (int r = 0; r < 4; ++r)
                acc[mf][nf][r] = 0.0f;

    // ---- Main loop over 128 reduction chunks (c = chunk>>1, k base = (chunk&1)*32) ----
    for (int chunk = 0; chunk < NCHUNK; ++chunk) {
        // issue copy of next chunk into the other buffer (safe: the last
        // readers of that buffer finished at the sync ending chunk-1)
        if (chunk + 1 < NCHUNK) {
            const uint32_t dstb = wsm_base + ((chunk + 1) & 1) * (WSM_WORDS * 4);
            const int kk0 = (chunk + 1) * BK;
#pragma unroll
            for (int j = 0; j < 4; ++j) {
                int g = j * 256 + tid;
                int f = g >> 3;
                int q = g & 7;
                cp_async16(dstb + (uint32_t)(f * WS + q * 4) * 4,
                           w + (size_t)f * K_RED + kk0 + q * 4);
            }
            cp_commit();
            cp_wait<1>();      // current chunk's copy complete
        } else {
            cp_wait<0>();
        }
        __syncthreads();       // all threads' copies visible block-wide

        const float* wb = wsm + (chunk & 1) * WSM_WORDS;
        const int c  = chunk >> 1;
        const int kb = (chunk & 1) << 5;           // 0 or 32
        const unsigned* xc = xs + c * TW;

#pragma unroll
        for (int s = 0; s < 4; ++s) {              // 4 k-steps of 8
            const int kcol = kb + s * 8 + tig;     // k for A fragment cols
            unsigned a[4][4];
#pragma unroll
            for (int mf = 0; mf < 4; ++mf) {
                const int r = warp_m * 64 + mf * 16 + gid;   // t row
                const unsigned* p = xc + r + kcol;           // x[c][t0 + r + k]
                a[mf][0] = p[0];      // (row,   col)
                a[mf][1] = p[8];      // (row+8, col)
                a[mf][2] = p[4];      // (row,   col+4)
                a[mf][3] = p[12];     // (row+8, col+4)
            }
            const int kkl = s * 8 + tig;           // local kk within chunk
            unsigned bfr[4][2];
#pragma unroll
            for (int nf = 0; nf < 4; ++nf) {
                const int f = warp_n * 32 + nf * 8 + gid;
                bfr[nf][0] = f2tf(wb[f * WS + kkl]);
                bfr[nf][1] = f2tf(wb[f * WS + kkl + 4]);
            }
#pragma unroll
            for (int mf = 0; mf < 4; ++mf)
#pragma unroll
                for (int nf = 0; nf < 4; ++nf)
                    mma_tf32(acc[mf][nf], a[mf][0], a[mf][1], a[mf][2], a[mf][3],
                             bfr[nf][0], bfr[nf][1]);
        }

        __syncthreads();       // protect this buffer before next-next copy lands
    }

    // ---- Epilogue: add bias, store out[n][f][t] ----
    float* outg = out + (size_t)n * F_OUT * OUT_W;
#pragma unroll
    for (int nf = 0; nf < 4; ++nf) {
        const int f0 = warp_n * 32 + nf * 8 + 2 * tig;
        const float b0v = bias[f0];
        const float b1v = bias[f0 + 1];
#pragma unroll
        for (int mf = 0; mf < 4; ++mf) {
            const int t_lo = t0 + warp_m * 64 + mf * 16 + gid;
            const int t_hi = t_lo + 8;
            if (t_lo < OUT_W) {
                outg[(size_t)f0 * OUT_W + t_lo]       = acc[mf][nf][0] + b0v;
                outg[(size_t)(f0 + 1) * OUT_W + t_lo] = acc[mf][nf][1] + b1v;
            }
            if (t_hi < OUT_W) {
                outg[(size_t)f0 * OUT_W + t_hi]       = acc[mf][nf][2] + b0v;
                outg[(size_t)(f0 + 1) * OUT_W + t_hi] = acc[mf][nf][3] + b1v;
            }
        }
    }
}

extern "C" void kernel_launch(void* const* d_in, const int* in_sizes, int n_in,
                              void* d_out, int out_size) {
    // Identify inputs by element count (robust to metadata ordering):
    // x: 32*64*4096 = 8388608, w: 128*64*64 = 524288, b: 128
    const float* x = nullptr;
    const float* w = nullptr;
    const float* b = nullptr;
    for (int i = 0; i < n_in; ++i) {
        const int s = in_sizes[i];
        if (s == N_BATCH * C_IN * W_IN)      x = (const float*)d_in[i];
        else if (s == F_OUT * C_IN * K_W)    w = (const float*)d_in[i];
        else if (s == F_OUT)                 b = (const float*)d_in[i];
    }

    cudaFuncSetAttribute(conv1d_tf32_kernel,
                         cudaFuncAttributeMaxDynamicSharedMemorySize, SMEM_BYTES);

    dim3 grid((OUT_W + BM - 1) / BM, N_BATCH);   // (32, 32)
    conv1d_tf32_kernel<<<grid, 256, SMEM_BYTES>>>(x, w, b, (float*)d_out);
}

// round 8
// speedup vs baseline: 1.2454x; 1.0893x over previous
#include <cuda_runtime.h>
#include <cstdint>

// Problem constants (from reference: x[32,64,4096], w[128,64,64], b[128])
#define N_BATCH 32
#define C_IN    64
#define W_IN    4096
#define F_OUT   128
#define K_W     64
#define OUT_W   (W_IN - K_W + 1)     // 4033
#define K_RED   (C_IN * K_W)         // 4096

// Tiling
#define BM      128                  // output t positions per block
#define TW      192                  // x window stride (BM + 64), padded
#define WS      36                   // w_s row stride (32 + 4) -> conflict-free
#define BK      32                   // reduction chunk (half of one channel's taps)
#define NCHUNK  (K_RED / BK)         // 128
#define NBUF    3                    // triple-buffered w staging

#define XS_WORDS  (C_IN * TW)                     // 12288 words = 48 KB
#define WSM_WORDS (F_OUT * WS)                    // 4608 words  = 18 KB
#define SMEM_BYTES ((XS_WORDS + NBUF * WSM_WORDS) * 4)   // 104448 B

// w pre-converted to tf32 bits (2 MB device scratch; static global = legal)
__device__ unsigned g_wtf[F_OUT * K_RED];

// Round-to-nearest fp32 -> tf32 (unbiased; raw truncation would bias the
// K=4096 reduction and blow the 1e-3 tolerance).
__device__ __forceinline__ unsigned f2tf(float f) {
    unsigned u;
    asm("cvt.rna.tf32.f32 %0, %1;" : "=r"(u) : "f"(f));
    return u;
}

__device__ __forceinline__ void mma_tf32(float c[4],
                                         unsigned a0, unsigned a1, unsigned a2, unsigned a3,
                                         unsigned b0, unsigned b1) {
    asm volatile(
        "mma.sync.aligned.m16n8k8.row.col.f32.tf32.tf32.f32 "
        "{%0,%1,%2,%3}, {%4,%5,%6,%7}, {%8,%9}, {%0,%1,%2,%3};"
        : "+f"(c[0]), "+f"(c[1]), "+f"(c[2]), "+f"(c[3])
        : "r"(a0), "r"(a1), "r"(a2), "r"(a3), "r"(b0), "r"(b1));
}

__device__ __forceinline__ void cp_async16(uint32_t smem_addr, const void* gptr) {
    asm volatile("cp.async.cg.shared.global [%0], [%1], 16;"
                 :: "r"(smem_addr), "l"(gptr));
}
__device__ __forceinline__ void cp_commit() {
    asm volatile("cp.async.commit_group;");
}
template <int N>
__device__ __forceinline__ void cp_wait() {
    asm volatile("cp.async.wait_group %0;" :: "n"(N));
}

// ---- w conversion kernel: fp32 -> tf32 bits, run once per launch ----
extern "C" __global__ void __launch_bounds__(256)
convert_w_kernel(const float* __restrict__ w) {
    int i = blockIdx.x * 256 + threadIdx.x;
    g_wtf[i] = f2tf(w[i]);
}

extern "C" __global__ void __launch_bounds__(256, 2)
conv1d_tf32_kernel(const float* __restrict__ x,
                   const float* __restrict__ bias,
                   float* __restrict__ out)
{
    extern __shared__ unsigned smem[];
    unsigned* xs  = smem;                 // [C_IN][TW]       x window, tf32 bits
    unsigned* wsm = smem + XS_WORDS;      // [NBUF][F_OUT][WS] w stage, tf32 bits

    const int tid  = threadIdx.x;
    const int lane = tid & 31;
    const int wid  = tid >> 5;
    const int gid  = lane >> 2;           // mma fragment groupID
    const int tig  = lane & 3;            // mma fragment threadID-in-group
    const int warp_m = wid & 1;           // 2 m-tiles of 64
    const int warp_n = wid >> 1;          // 4 n-tiles of 32

    const int t0 = blockIdx.x * BM;       // output t base
    const int n  = blockIdx.y;            // batch index

    const float* xg = x + (size_t)n * C_IN * W_IN;

    const uint32_t wsm_base = (uint32_t)__cvta_generic_to_shared(wsm);
    // Per-thread cp.async slice: thread handles (f, q): g = j*256+tid, f=g>>3, q=g&7
    const int cp_f = tid >> 3;            // with j folded below
    const int cp_q = tid & 7;

    // ---- Kick off w chunk 0 copy into buffer 0 ----
#pragma unroll
    for (int j = 0; j < 4; ++j) {
        int f = cp_f + j * 32;
        cp_async16(wsm_base + (uint32_t)(f * WS + cp_q * 4) * 4,
                   g_wtf + (size_t)f * K_RED + cp_q * 4);
    }
    cp_commit();

    // ---- Load x window [64 x 192] (t0 .. t0+191), zero-pad past W, cvt tf32 ----
    for (int i = tid; i < XS_WORDS; i += 256) {
        int c  = i / TW;
        int tw = i - c * TW;
        int t  = t0 + tw;
        float v = (t < W_IN) ? xg[c * W_IN + t] : 0.0f;
        xs[i] = f2tf(v);
    }

    float acc[4][4][4];
#pragma unroll
    for (int mf = 0; mf < 4; ++mf)
#pragma unroll
        for (int nf = 0; nf < 4; ++nf)
#pragma unroll
            for (int r = 0; r < 4; ++r)
                acc[mf][nf][r] = 0.0f;

    // ---- Main loop: 128 reduction chunks (c = chunk>>1, k base = (chunk&1)*32)
    int buf = 0;
    for (int chunk = 0; chunk < NCHUNK; ++chunk) {
        const int nbuf = (buf == NBUF - 1) ? 0 : buf + 1;
        // issue copy of next chunk into buffer nbuf. Its previous readers were
        // chunk-2; every thread passed the chunk-1 sync after finishing them.
        if (chunk + 1 < NCHUNK) {
            const uint32_t dstb = wsm_base + (uint32_t)nbuf * (WSM_WORDS * 4);
            const int kk0 = (chunk + 1) * BK;
#pragma unroll
            for (int j = 0; j < 4; ++j) {
                int f = cp_f + j * 32;
                cp_async16(dstb + (uint32_t)(f * WS + cp_q * 4) * 4,
                           g_wtf + (size_t)f * K_RED + kk0 + cp_q * 4);
            }
            cp_commit();
            cp_wait<1>();      // current chunk's group complete
        } else {
            cp_wait<0>();
        }
        __syncthreads();       // copies visible block-wide; prior buf reads done

        const unsigned* wb = wsm + buf * WSM_WORDS;
        const int c  = chunk >> 1;
        const int kb = (chunk & 1) << 5;           // 0 or 32

        // A operand is Hankel: A[m][k] = x[t0+m+k]. All fragments for this
        // chunk come from a 22-word stride-4 register window.
        const unsigned* abase = xs + c * TW + warp_m * 64 + gid + kb + tig;
        unsigned av[22];
#pragma unroll
        for (int i = 0; i < 22; ++i) av[i] = abase[4 * i];

#pragma unroll
        for (int s = 0; s < 4; ++s) {              // 4 k-steps of 8
            const int kkl = s * 8 + tig;           // local kk within chunk
            unsigned bfr[4][2];
#pragma unroll
            for (int nf = 0; nf < 4; ++nf) {
                const int f = warp_n * 32 + nf * 8 + gid;
                bfr[nf][0] = wb[f * WS + kkl];
                bfr[nf][1] = wb[f * WS + kkl + 4];
            }
#pragma unroll
            for (int mf = 0; mf < 4; ++mf) {
                const unsigned a0 = av[4 * mf + 2 * s];      // (row,   col)
                const unsigned a1 = av[4 * mf + 2 * s + 2];  // (row+8, col)
                const unsigned a2 = av[4 * mf + 2 * s + 1];  // (row,   col+4)
                const unsigned a3 = av[4 * mf + 2 * s + 3];  // (row+8, col+4)
#pragma unroll
                for (int nf = 0; nf < 4; ++nf)
                    mma_tf32(acc[mf][nf], a0, a1, a2, a3, bfr[nf][0], bfr[nf][1]);
            }
        }
        buf = nbuf;
    }

    // ---- Epilogue: add bias, store out[n][f][t] ----
    float* outg = out + (size_t)n * F_OUT * OUT_W;
#pragma unroll
    for (int nf = 0; nf < 4; ++nf) {
        const int f0 = warp_n * 32 + nf * 8 + 2 * tig;
        const float b0v = bias[f0];
        const float b1v = bias[f0 + 1];
#pragma unroll
        for (int mf = 0; mf < 4; ++mf) {
            const int t_lo = t0 + warp_m * 64 + mf * 16 + gid;
            const int t_hi = t_lo + 8;
            if (t_lo < OUT_W) {
                outg[(size_t)f0 * OUT_W + t_lo]       = acc[mf][nf][0] + b0v;
                outg[(size_t)(f0 + 1) * OUT_W + t_lo] = acc[mf][nf][1] + b1v;
            }
            if (t_hi < OUT_W) {
                outg[(size_t)f0 * OUT_W + t_hi]       = acc[mf][nf][2] + b0v;
                outg[(size_t)(f0 + 1) * OUT_W + t_hi] = acc[mf][nf][3] + b1v;
            }
        }
    }
}

extern "C" void kernel_launch(void* const* d_in, const int* in_sizes, int n_in,
                              void* d_out, int out_size) {
    // Identify inputs by element count (robust to metadata ordering):
    // x: 32*64*4096 = 8388608, w: 128*64*64 = 524288, b: 128
    const float* x = nullptr;
    const float* w = nullptr;
    const float* b = nullptr;
    for (int i = 0; i < n_in; ++i) {
        const int s = in_sizes[i];
        if (s == N_BATCH * C_IN * W_IN)      x = (const float*)d_in[i];
        else if (s == F_OUT * C_IN * K_W)    w = (const float*)d_in[i];
        else if (s == F_OUT)                 b = (const float*)d_in[i];
    }

    // 1) Pre-convert w to tf32 bits (2 MB, ~3 us)
    convert_w_kernel<<<(F_OUT * K_RED) / 256, 256>>>(w);

    // 2) Main implicit-GEMM conv
    cudaFuncSetAttribute(conv1d_tf32_kernel,
                         cudaFuncAttributeMaxDynamicSharedMemorySize, SMEM_BYTES);
    dim3 grid((OUT_W + BM - 1) / BM, N_BATCH);   // (32, 32)
    conv1d_tf32_kernel<<<grid, 256, SMEM_BYTES>>>(x, b, (float*)d_out);
}